// round 1
// baseline (speedup 1.0000x reference)
#include <cuda_runtime.h>
#include <math.h>

#define N_RES   30000
#define N_ATOMS 6
#define N_EDGES 300000
#define HIDDEN  128
#define L_TOT   (N_RES * N_ATOMS)
#define EPSF    1e-6f
#define E_FEAT  688
#define V_FEAT  44

// scratch (static device allocations are allowed)
__device__ float g_Q[N_RES * 9];     // per-residue frame, Q[k*3+j] = basis_j[k] (cols b,n,c)
__device__ int   g_valid[N_RES];     // q_valid

struct F3 { float x, y, z; };
__device__ __forceinline__ F3 f3(float x, float y, float z) { F3 r; r.x = x; r.y = y; r.z = z; return r; }
__device__ __forceinline__ F3 sub3(F3 a, F3 b) { return f3(a.x - b.x, a.y - b.y, a.z - b.z); }
__device__ __forceinline__ float dot3(F3 a, F3 b) { return a.x * b.x + a.y * b.y + a.z * b.z; }
__device__ __forceinline__ F3 cross3(F3 a, F3 b) {
    return f3(a.y * b.z - a.z * b.y, a.z * b.x - a.x * b.z, a.x * b.y - a.y * b.x);
}
__device__ __forceinline__ F3 nrm3(F3 v) {
    float n = sqrtf(dot3(v, v));
    float r = 1.0f / fmaxf(n, 1e-12f);
    return f3(v.x * r, v.y * r, v.z * r);
}
__device__ __forceinline__ float sgn(float x) { return (x > 0.f) ? 1.f : ((x < 0.f) ? -1.f : 0.f); }
__device__ __forceinline__ F3 ld3(const float* p) { return f3(p[0], p[1], p[2]); }

// ---------------------------------------------------------------------------
// Kernel 1: per-residue local frames Q + q_valid
// ---------------------------------------------------------------------------
__global__ void frames_kernel(const float* __restrict__ cX, const int* __restrict__ batch) {
    int r = blockIdx.x * blockDim.x + threadIdx.x;
    if (r >= N_RES) return;
    float Qm[9];
#pragma unroll
    for (int i = 0; i < 9; i++) Qm[i] = 0.f;
    int valid = 0;
    if (r > 0 && r < N_RES - 1) {
        int br = batch[r];
        bool boundary      = (batch[r - 1] != br);
        bool boundary_next = (batch[r + 1] != br);
        if (!boundary && !boundary_next) {
            valid = 1;
            F3 p0 = ld3(cX + (r - 1) * 3);
            F3 p1 = ld3(cX + r * 3);
            F3 p2 = ld3(cX + (r + 1) * 3);
            F3 du0 = nrm3(sub3(p1, p0));
            F3 du1 = nrm3(sub3(p2, p1));
            F3 b = nrm3(sub3(du0, du1));
            F3 n = nrm3(cross3(du0, du1));
            F3 c = cross3(b, n);
            Qm[0] = b.x; Qm[1] = n.x; Qm[2] = c.x;
            Qm[3] = b.y; Qm[4] = n.y; Qm[5] = c.y;
            Qm[6] = b.z; Qm[7] = n.z; Qm[8] = c.z;
        }
    }
#pragma unroll
    for (int i = 0; i < 9; i++) g_Q[r * 9 + i] = Qm[i];
    g_valid[r] = valid;
}

// ---------------------------------------------------------------------------
// Kernel 2: node features (44) -> @node_W -> LN. One warp per residue.
// ---------------------------------------------------------------------------
__global__ void node_kernel(const float* __restrict__ coords,   // Xf flat [L_TOT][3]
                            const float* __restrict__ cX,
                            const float* __restrict__ nW,       // [44][128]
                            const float* __restrict__ nb,
                            const float* __restrict__ lnw,
                            const float* __restrict__ lnb,
                            const int* __restrict__ batch,
                            float* __restrict__ out) {
    __shared__ float sW[V_FEAT * HIDDEN];
    __shared__ float sfeat[8][V_FEAT];
    int tid = threadIdx.x;
    for (int i = tid; i < V_FEAT * HIDDEN; i += 256) sW[i] = nW[i];

    int w = tid >> 5, lane = tid & 31;
    int r = blockIdx.x * 8 + w;

    int br = batch[r];
    bool boundary      = (r > 0) && (batch[r - 1] != br);
    bool boundary_next = (r < N_RES - 1) && (batch[r + 1] != br);
    const float* Xf = coords;

    if (lane < 6) {
        // dihedral features for atom a
        int a = lane;
        int k = r * N_ATOMS + a;
        bool m = (k > 0) && (k < L_TOT - 2) &&
                 !(boundary && a == 0) && !(boundary_next && a >= N_ATOMS - 2);
        float s = 0.f, c = 0.f;
        if (m) {
            F3 x0 = ld3(Xf + (k - 1) * 3), x1 = ld3(Xf + k * 3);
            F3 x2 = ld3(Xf + (k + 1) * 3), x3 = ld3(Xf + (k + 2) * 3);
            F3 u0 = nrm3(sub3(x1, x0));
            F3 u1 = nrm3(sub3(x2, x1));
            F3 u2 = nrm3(sub3(x3, x2));
            F3 c1 = nrm3(cross3(u0, u1));
            F3 c2 = nrm3(cross3(u1, u2));
            float cd = fminf(fmaxf(dot3(c1, c2), -1.f + EPSF), 1.f - EPSF);
            float dih = acosf(cd) * sgn(dot3(c2, u0));
            sincosf(dih, &s, &c);
        }
        sfeat[w][2 * a]     = s;
        sfeat[w][2 * a + 1] = c;
    } else if (lane < 12) {
        // angle features for atom a
        int a = lane - 6;
        int k = r * N_ATOMS + a;
        bool m = (k > 0) && (k < L_TOT - 1) &&
                 !(boundary && a == 0) && !(boundary_next && a == N_ATOMS - 1);
        float sa = 0.f, ca = 0.f;
        if (m) {
            F3 x0 = ld3(Xf + (k - 1) * 3), x1 = ld3(Xf + k * 3), x2 = ld3(Xf + (k + 1) * 3);
            F3 d0 = nrm3(sub3(x0, x1));
            F3 d1 = nrm3(sub3(x2, x1));
            ca = dot3(d0, d1);
            sa = sqrtf(1.f - ca * ca + EPSF);
        }
        sfeat[w][12 + 2 * a] = sa;
        sfeat[w][13 + 2 * a] = ca;
    } else if (lane < 17) {
        // intra dist/direct for non-central atom j
        int j = lane - 12;
        int a = (j == 0) ? 0 : (j + 1);   // keep = {0,2,3,4,5}
        F3 d = sub3(ld3(coords + (r * N_ATOMS + a) * 3), ld3(cX + r * 3));
        float nn = dot3(d, d);
        sfeat[w][24 + j] = logf(sqrtf(nn + EPSF));
        float rn = 1.0f / fmaxf(sqrtf(nn), 1e-12f);
        float hx = d.x * rn, hy = d.y * rn, hz = d.z * rn;
        const float* Qr = g_Q + r * 9;
#pragma unroll
        for (int i = 0; i < 3; i++)
            sfeat[w][29 + 3 * j + i] = Qr[i] * hx + Qr[3 + i] * hy + Qr[6 + i] * hz;
    }
    __syncthreads();

    // matvec: channels c = lane + 32*q
    float y[4];
#pragma unroll
    for (int q = 0; q < 4; q++) {
        int c = lane + 32 * q;
        float acc = nb[c];
#pragma unroll
        for (int j = 0; j < V_FEAT; j++)
            acc = fmaf(sfeat[w][j], sW[j * HIDDEN + c], acc);
        y[q] = acc;
    }
    // layernorm over 128 channels (within warp)
    float tot = y[0] + y[1] + y[2] + y[3];
#pragma unroll
    for (int o = 16; o > 0; o >>= 1) tot += __shfl_xor_sync(0xffffffffu, tot, o);
    float mean = tot * (1.0f / HIDDEN);
    float v = 0.f;
#pragma unroll
    for (int q = 0; q < 4; q++) { float d = y[q] - mean; v += d * d; }
#pragma unroll
    for (int o = 16; o > 0; o >>= 1) v += __shfl_xor_sync(0xffffffffu, v, o);
    float inv = 1.0f / sqrtf(v * (1.0f / HIDDEN) + 1e-5f);
#pragma unroll
    for (int q = 0; q < 4; q++) {
        int c = lane + 32 * q;
        out[r * HIDDEN + c] = (y[q] - mean) * inv * lnw[c] + lnb[c];
    }
}

// ---------------------------------------------------------------------------
// Kernel 3: edge features (688) -> @edge_W -> LN.
// 128 threads/block, 16 edges/block (one warp owns 4 edges).
// ---------------------------------------------------------------------------
__global__ void __launch_bounds__(128)
edge_kernel(const float* __restrict__ coords,
            const float* __restrict__ eW,     // [688][128]
            const float* __restrict__ eb,
            const float* __restrict__ lnw,
            const float* __restrict__ lnb,
            const int* __restrict__ ei,       // [2][N_EDGES]
            float* __restrict__ out) {
    __shared__ float sf[16 * E_FEAT];   // 44032 B
    int tid = threadIdx.x;
    int lane = tid & 31;
    int ty = tid >> 5;                  // 0..3
    int tile = blockIdx.x * 16;

    // ------- Phase A: features into smem -------
    for (int el = 0; el < 4; el++) {
        int erow = ty * 4 + el;
        int e = tile + erow;
        int src = ei[e];
        int tgt = ei[N_EDGES + e];
        float* f = &sf[erow * E_FEAT];

        float qt[9];
#pragma unroll
        for (int i = 0; i < 9; i++) qt[i] = g_Q[tgt * 9 + i];

        // 36 atom pairs: p = t*6 + s
        for (int p = lane; p < 36; p += 32) {
            int t = p / 6, s = p - t * 6;
            F3 A = ld3(coords + (src * N_ATOMS + s) * 3);
            F3 B = ld3(coords + (tgt * N_ATOMS + t) * 3);
            float dx = A.x - B.x, dy = A.y - B.y, dz = A.z - B.z;
            float nn = dx * dx + dy * dy + dz * dz;
            float D = sqrtf(nn + EPSF);
            float* fr = f + 4 + p * 16;
#pragma unroll
            for (int i = 0; i < 16; i++) {
                float z = (D - (float)i * (20.0f / 15.0f)) * 0.8f;  // /sigma, sigma=1.25
                fr[i] = __expf(-z * z);
            }
            float rn = 1.0f / fmaxf(sqrtf(nn), 1e-12f);
            float hx = dx * rn, hy = dy * rn, hz = dz * rn;
            float* fd = f + 4 + 576 + p * 3;
            fd[0] = qt[0] * hx + qt[3] * hy + qt[6] * hz;
            fd[1] = qt[1] * hx + qt[4] * hy + qt[7] * hz;
            fd[2] = qt[2] * hx + qt[5] * hy + qt[8] * hz;
        }
        if (lane == 0) {
            float qx = 0.f, qy = 0.f, qz = 0.f, qw = 0.f;
            if (g_valid[src] && g_valid[tgt]) {
                float qs[9];
#pragma unroll
                for (int i = 0; i < 9; i++) qs[i] = g_Q[src * 9 + i];
                // R[i][j] = sum_k qt[k*3+i]*qs[k*3+j]
                float R[3][3];
#pragma unroll
                for (int i = 0; i < 3; i++)
#pragma unroll
                    for (int j = 0; j < 3; j++)
                        R[i][j] = qt[i] * qs[j] + qt[3 + i] * qs[3 + j] + qt[6 + i] * qs[6 + j];
                float Rxx = R[0][0], Ryy = R[1][1], Rzz = R[2][2];
                float m0 = 0.5f * sqrtf(fabsf(1.f + Rxx - Ryy - Rzz));
                float m1 = 0.5f * sqrtf(fabsf(1.f - Rxx + Ryy - Rzz));
                float m2 = 0.5f * sqrtf(fabsf(1.f - Rxx - Ryy + Rzz));
                qx = sgn(R[2][1] - R[1][2]) * m0;
                qy = sgn(R[0][2] - R[2][0]) * m1;
                qz = sgn(R[1][0] - R[0][1]) * m2;
                qw = 0.5f * sqrtf(fmaxf(0.f, 1.f + Rxx + Ryy + Rzz));
                float n = sqrtf(qx * qx + qy * qy + qz * qz + qw * qw);
                float rq = 1.0f / fmaxf(n, 1e-12f);
                qx *= rq; qy *= rq; qz *= rq; qw *= rq;
            }
            f[0] = qx; f[1] = qy; f[2] = qz; f[3] = qw;
        }
    }
    __syncthreads();

    // ------- Phase B: GEMM. Thread owns channels 4*lane..+3 of 4 edges -------
    float acc[4][4];
#pragma unroll
    for (int e = 0; e < 4; e++)
#pragma unroll
        for (int j = 0; j < 4; j++) acc[e][j] = 0.f;

    const float4* W4 = (const float4*)eW;   // [688][32]
    const float* fb = &sf[(ty * 4) * E_FEAT];

    for (int k = 0; k < E_FEAT; k += 4) {
        float4 w0 = W4[(k + 0) * 32 + lane];
        float4 w1 = W4[(k + 1) * 32 + lane];
        float4 w2 = W4[(k + 2) * 32 + lane];
        float4 w3 = W4[(k + 3) * 32 + lane];
#pragma unroll
        for (int e = 0; e < 4; e++) {
            float4 fv = *(const float4*)(fb + e * E_FEAT + k);
            acc[e][0] = fmaf(fv.w, w3.x, fmaf(fv.z, w2.x, fmaf(fv.y, w1.x, fmaf(fv.x, w0.x, acc[e][0]))));
            acc[e][1] = fmaf(fv.w, w3.y, fmaf(fv.z, w2.y, fmaf(fv.y, w1.y, fmaf(fv.x, w0.y, acc[e][1]))));
            acc[e][2] = fmaf(fv.w, w3.z, fmaf(fv.z, w2.z, fmaf(fv.y, w1.z, fmaf(fv.x, w0.z, acc[e][2]))));
            acc[e][3] = fmaf(fv.w, w3.w, fmaf(fv.z, w2.w, fmaf(fv.y, w1.w, fmaf(fv.x, w0.w, acc[e][3]))));
        }
    }

    // bias
    float4 bv = ((const float4*)eb)[lane];
#pragma unroll
    for (int e = 0; e < 4; e++) {
        acc[e][0] += bv.x; acc[e][1] += bv.y; acc[e][2] += bv.z; acc[e][3] += bv.w;
    }

    // layernorm per edge (warp holds all 128 channels of its 4 edges)
    float red[4];
#pragma unroll
    for (int e = 0; e < 4; e++) red[e] = acc[e][0] + acc[e][1] + acc[e][2] + acc[e][3];
#pragma unroll
    for (int o = 16; o > 0; o >>= 1)
#pragma unroll
        for (int e = 0; e < 4; e++) red[e] += __shfl_xor_sync(0xffffffffu, red[e], o);
    float mean[4];
#pragma unroll
    for (int e = 0; e < 4; e++) mean[e] = red[e] * (1.0f / HIDDEN);
    float vr[4];
#pragma unroll
    for (int e = 0; e < 4; e++) {
        float v = 0.f;
#pragma unroll
        for (int j = 0; j < 4; j++) { float d = acc[e][j] - mean[e]; v += d * d; }
        vr[e] = v;
    }
#pragma unroll
    for (int o = 16; o > 0; o >>= 1)
#pragma unroll
        for (int e = 0; e < 4; e++) vr[e] += __shfl_xor_sync(0xffffffffu, vr[e], o);

    float4 lw = ((const float4*)lnw)[lane];
    float4 lb = ((const float4*)lnb)[lane];
#pragma unroll
    for (int e = 0; e < 4; e++) {
        float inv = 1.0f / sqrtf(vr[e] * (1.0f / HIDDEN) + 1e-5f);
        int eg = tile + ty * 4 + e;
        float4 o4;
        o4.x = (acc[e][0] - mean[e]) * inv * lw.x + lb.x;
        o4.y = (acc[e][1] - mean[e]) * inv * lw.y + lb.y;
        o4.z = (acc[e][2] - mean[e]) * inv * lw.z + lb.z;
        o4.w = (acc[e][3] - mean[e]) * inv * lw.w + lb.w;
        ((float4*)(out + (size_t)eg * HIDDEN))[lane] = o4;
    }
}

// ---------------------------------------------------------------------------
extern "C" void kernel_launch(void* const* d_in, const int* in_sizes, int n_in,
                              void* d_out, int out_size) {
    const float* coords     = (const float*)d_in[0];
    const float* cX         = (const float*)d_in[1];
    const float* node_W     = (const float*)d_in[2];
    const float* node_b     = (const float*)d_in[3];
    const float* node_ln_w  = (const float*)d_in[4];
    const float* node_ln_b  = (const float*)d_in[5];
    const float* edge_W     = (const float*)d_in[6];
    const float* edge_b     = (const float*)d_in[7];
    const float* edge_ln_w  = (const float*)d_in[8];
    const float* edge_ln_b  = (const float*)d_in[9];
    const int*   batch      = (const int*)d_in[10];
    const int*   edge_index = (const int*)d_in[11];
    float* out = (float*)d_out;

    frames_kernel<<<(N_RES + 255) / 256, 256>>>(cX, batch);
    node_kernel<<<N_RES / 8, 256>>>(coords, cX, node_W, node_b, node_ln_w, node_ln_b,
                                    batch, out);
    edge_kernel<<<N_EDGES / 16, 128>>>(coords, edge_W, edge_b, edge_ln_w, edge_ln_b,
                                       edge_index, out + (size_t)N_RES * HIDDEN);
}

// round 2
// speedup vs baseline: 1.0033x; 1.0033x over previous
#include <cuda_runtime.h>
#include <math.h>

#define N_RES   30000
#define N_ATOMS 6
#define N_EDGES 300000
#define HIDDEN  128
#define L_TOT   (N_RES * N_ATOMS)
#define EPSF    1e-6f
#define E_FEAT  688
#define V_FEAT  44

// scratch (static device allocations are allowed)
__device__ float g_Q[N_RES * 9];     // per-residue frame, Q[k*3+j] = basis_j[k] (cols b,n,c)
__device__ int   g_valid[N_RES];     // q_valid

struct F3 { float x, y, z; };
__device__ __forceinline__ F3 f3(float x, float y, float z) { F3 r; r.x = x; r.y = y; r.z = z; return r; }
__device__ __forceinline__ F3 sub3(F3 a, F3 b) { return f3(a.x - b.x, a.y - b.y, a.z - b.z); }
__device__ __forceinline__ float dot3(F3 a, F3 b) { return a.x * b.x + a.y * b.y + a.z * b.z; }
__device__ __forceinline__ F3 cross3(F3 a, F3 b) {
    return f3(a.y * b.z - a.z * b.y, a.z * b.x - a.x * b.z, a.x * b.y - a.y * b.x);
}
__device__ __forceinline__ F3 nrm3(F3 v) {
    float n = sqrtf(dot3(v, v));
    float r = 1.0f / fmaxf(n, 1e-12f);
    return f3(v.x * r, v.y * r, v.z * r);
}
__device__ __forceinline__ float sgn(float x) { return (x > 0.f) ? 1.f : ((x < 0.f) ? -1.f : 0.f); }
__device__ __forceinline__ F3 ld3(const float* p) { return f3(p[0], p[1], p[2]); }

// ---------------------------------------------------------------------------
// Kernel 1: per-residue local frames Q + q_valid
// ---------------------------------------------------------------------------
__global__ void frames_kernel(const float* __restrict__ cX, const int* __restrict__ batch) {
    int r = blockIdx.x * blockDim.x + threadIdx.x;
    if (r >= N_RES) return;
    float Qm[9];
#pragma unroll
    for (int i = 0; i < 9; i++) Qm[i] = 0.f;
    int valid = 0;
    if (r > 0 && r < N_RES - 1) {
        int br = batch[r];
        bool boundary      = (batch[r - 1] != br);
        bool boundary_next = (batch[r + 1] != br);
        if (!boundary && !boundary_next) {
            valid = 1;
            F3 p0 = ld3(cX + (r - 1) * 3);
            F3 p1 = ld3(cX + r * 3);
            F3 p2 = ld3(cX + (r + 1) * 3);
            F3 du0 = nrm3(sub3(p1, p0));
            F3 du1 = nrm3(sub3(p2, p1));
            F3 b = nrm3(sub3(du0, du1));
            F3 n = nrm3(cross3(du0, du1));
            F3 c = cross3(b, n);
            Qm[0] = b.x; Qm[1] = n.x; Qm[2] = c.x;
            Qm[3] = b.y; Qm[4] = n.y; Qm[5] = c.y;
            Qm[6] = b.z; Qm[7] = n.z; Qm[8] = c.z;
        }
    }
#pragma unroll
    for (int i = 0; i < 9; i++) g_Q[r * 9 + i] = Qm[i];
    g_valid[r] = valid;
}

// ---------------------------------------------------------------------------
// Kernel 2: node features (44) -> @node_W -> LN. One warp per residue.
// ---------------------------------------------------------------------------
__global__ void node_kernel(const float* __restrict__ coords,   // Xf flat [L_TOT][3]
                            const float* __restrict__ cX,
                            const float* __restrict__ nW,       // [44][128]
                            const float* __restrict__ nb,
                            const float* __restrict__ lnw,
                            const float* __restrict__ lnb,
                            const int* __restrict__ batch,
                            float* __restrict__ out) {
    __shared__ float sW[V_FEAT * HIDDEN];
    __shared__ float sfeat[8][V_FEAT];
    int tid = threadIdx.x;
    for (int i = tid; i < V_FEAT * HIDDEN; i += 256) sW[i] = nW[i];

    int w = tid >> 5, lane = tid & 31;
    int r = blockIdx.x * 8 + w;

    int br = batch[r];
    bool boundary      = (r > 0) && (batch[r - 1] != br);
    bool boundary_next = (r < N_RES - 1) && (batch[r + 1] != br);
    const float* Xf = coords;

    if (lane < 6) {
        // dihedral features for atom a
        int a = lane;
        int k = r * N_ATOMS + a;
        bool m = (k > 0) && (k < L_TOT - 2) &&
                 !(boundary && a == 0) && !(boundary_next && a >= N_ATOMS - 2);
        float s = 0.f, c = 0.f;
        if (m) {
            F3 x0 = ld3(Xf + (k - 1) * 3), x1 = ld3(Xf + k * 3);
            F3 x2 = ld3(Xf + (k + 1) * 3), x3 = ld3(Xf + (k + 2) * 3);
            F3 u0 = nrm3(sub3(x1, x0));
            F3 u1 = nrm3(sub3(x2, x1));
            F3 u2 = nrm3(sub3(x3, x2));
            F3 c1 = nrm3(cross3(u0, u1));
            F3 c2 = nrm3(cross3(u1, u2));
            float cd = fminf(fmaxf(dot3(c1, c2), -1.f + EPSF), 1.f - EPSF);
            float dih = acosf(cd) * sgn(dot3(c2, u0));
            sincosf(dih, &s, &c);
        }
        sfeat[w][2 * a]     = s;
        sfeat[w][2 * a + 1] = c;
    } else if (lane < 12) {
        // angle features for atom a
        int a = lane - 6;
        int k = r * N_ATOMS + a;
        bool m = (k > 0) && (k < L_TOT - 1) &&
                 !(boundary && a == 0) && !(boundary_next && a == N_ATOMS - 1);
        float sa = 0.f, ca = 0.f;
        if (m) {
            F3 x0 = ld3(Xf + (k - 1) * 3), x1 = ld3(Xf + k * 3), x2 = ld3(Xf + (k + 1) * 3);
            F3 d0 = nrm3(sub3(x0, x1));
            F3 d1 = nrm3(sub3(x2, x1));
            ca = dot3(d0, d1);
            sa = sqrtf(1.f - ca * ca + EPSF);
        }
        sfeat[w][12 + 2 * a] = sa;
        sfeat[w][13 + 2 * a] = ca;
    } else if (lane < 17) {
        // intra dist/direct for non-central atom j
        int j = lane - 12;
        int a = (j == 0) ? 0 : (j + 1);   // keep = {0,2,3,4,5}
        F3 d = sub3(ld3(coords + (r * N_ATOMS + a) * 3), ld3(cX + r * 3));
        float nn = dot3(d, d);
        sfeat[w][24 + j] = logf(sqrtf(nn + EPSF));
        float rn = 1.0f / fmaxf(sqrtf(nn), 1e-12f);
        float hx = d.x * rn, hy = d.y * rn, hz = d.z * rn;
        const float* Qr = g_Q + r * 9;
#pragma unroll
        for (int i = 0; i < 3; i++)
            sfeat[w][29 + 3 * j + i] = Qr[i] * hx + Qr[3 + i] * hy + Qr[6 + i] * hz;
    }
    __syncthreads();

    // matvec: channels c = lane + 32*q
    float y[4];
#pragma unroll
    for (int q = 0; q < 4; q++) {
        int c = lane + 32 * q;
        float acc = nb[c];
#pragma unroll
        for (int j = 0; j < V_FEAT; j++)
            acc = fmaf(sfeat[w][j], sW[j * HIDDEN + c], acc);
        y[q] = acc;
    }
    // layernorm over 128 channels (within warp)
    float tot = y[0] + y[1] + y[2] + y[3];
#pragma unroll
    for (int o = 16; o > 0; o >>= 1) tot += __shfl_xor_sync(0xffffffffu, tot, o);
    float mean = tot * (1.0f / HIDDEN);
    float v = 0.f;
#pragma unroll
    for (int q = 0; q < 4; q++) { float d = y[q] - mean; v += d * d; }
#pragma unroll
    for (int o = 16; o > 0; o >>= 1) v += __shfl_xor_sync(0xffffffffu, v, o);
    float inv = 1.0f / sqrtf(v * (1.0f / HIDDEN) + 1e-5f);
#pragma unroll
    for (int q = 0; q < 4; q++) {
        int c = lane + 32 * q;
        out[r * HIDDEN + c] = (y[q] - mean) * inv * lnw[c] + lnb[c];
    }
}

// ---------------------------------------------------------------------------
// Kernel 3: edge features (688) -> @edge_W -> LN.
// 128 threads/block, 16 edges/block (one warp owns 4 edges).
// ---------------------------------------------------------------------------
__global__ void __launch_bounds__(128)
edge_kernel(const float* __restrict__ coords,
            const float* __restrict__ eW,     // [688][128]
            const float* __restrict__ eb,
            const float* __restrict__ lnw,
            const float* __restrict__ lnb,
            const int* __restrict__ ei,       // [2][N_EDGES]
            float* __restrict__ out) {
    __shared__ float sf[16 * E_FEAT];   // 44032 B
    int tid = threadIdx.x;
    int lane = tid & 31;
    int ty = tid >> 5;                  // 0..3
    int tile = blockIdx.x * 16;

    // ------- Phase A: features into smem -------
    for (int el = 0; el < 4; el++) {
        int erow = ty * 4 + el;
        int e = tile + erow;
        int src = ei[e];
        int tgt = ei[N_EDGES + e];
        float* f = &sf[erow * E_FEAT];

        float qt[9];
#pragma unroll
        for (int i = 0; i < 9; i++) qt[i] = g_Q[tgt * 9 + i];

        // 36 atom pairs: p = t*6 + s
        for (int p = lane; p < 36; p += 32) {
            int t = p / 6, s = p - t * 6;
            F3 A = ld3(coords + (src * N_ATOMS + s) * 3);
            F3 B = ld3(coords + (tgt * N_ATOMS + t) * 3);
            float dx = A.x - B.x, dy = A.y - B.y, dz = A.z - B.z;
            float nn = dx * dx + dy * dy + dz * dz;
            float D = sqrtf(nn + EPSF);
            float* fr = f + 4 + p * 16;
#pragma unroll
            for (int i = 0; i < 16; i++) {
                float z = (D - (float)i * (20.0f / 15.0f)) * 0.8f;  // /sigma, sigma=1.25
                fr[i] = __expf(-z * z);
            }
            float rn = 1.0f / fmaxf(sqrtf(nn), 1e-12f);
            float hx = dx * rn, hy = dy * rn, hz = dz * rn;
            float* fd = f + 4 + 576 + p * 3;
            fd[0] = qt[0] * hx + qt[3] * hy + qt[6] * hz;
            fd[1] = qt[1] * hx + qt[4] * hy + qt[7] * hz;
            fd[2] = qt[2] * hx + qt[5] * hy + qt[8] * hz;
        }
        if (lane == 0) {
            float qx = 0.f, qy = 0.f, qz = 0.f, qw = 0.f;
            if (g_valid[src] && g_valid[tgt]) {
                float qs[9];
#pragma unroll
                for (int i = 0; i < 9; i++) qs[i] = g_Q[src * 9 + i];
                // R[i][j] = sum_k qt[k*3+i]*qs[k*3+j]
                float R[3][3];
#pragma unroll
                for (int i = 0; i < 3; i++)
#pragma unroll
                    for (int j = 0; j < 3; j++)
                        R[i][j] = qt[i] * qs[j] + qt[3 + i] * qs[3 + j] + qt[6 + i] * qs[6 + j];
                float Rxx = R[0][0], Ryy = R[1][1], Rzz = R[2][2];
                float m0 = 0.5f * sqrtf(fabsf(1.f + Rxx - Ryy - Rzz));
                float m1 = 0.5f * sqrtf(fabsf(1.f - Rxx + Ryy - Rzz));
                float m2 = 0.5f * sqrtf(fabsf(1.f - Rxx - Ryy + Rzz));
                qx = sgn(R[2][1] - R[1][2]) * m0;
                qy = sgn(R[0][2] - R[2][0]) * m1;
                qz = sgn(R[1][0] - R[0][1]) * m2;
                qw = 0.5f * sqrtf(fmaxf(0.f, 1.f + Rxx + Ryy + Rzz));
                float n = sqrtf(qx * qx + qy * qy + qz * qz + qw * qw);
                float rq = 1.0f / fmaxf(n, 1e-12f);
                qx *= rq; qy *= rq; qz *= rq; qw *= rq;
            }
            f[0] = qx; f[1] = qy; f[2] = qz; f[3] = qw;
        }
    }
    __syncthreads();

    // ------- Phase B: GEMM. Thread owns channels 4*lane..+3 of 4 edges -------
    float acc[4][4];
#pragma unroll
    for (int e = 0; e < 4; e++)
#pragma unroll
        for (int j = 0; j < 4; j++) acc[e][j] = 0.f;

    const float4* W4 = (const float4*)eW;   // [688][32]
    const float* fb = &sf[(ty * 4) * E_FEAT];

    for (int k = 0; k < E_FEAT; k += 4) {
        float4 w0 = W4[(k + 0) * 32 + lane];
        float4 w1 = W4[(k + 1) * 32 + lane];
        float4 w2 = W4[(k + 2) * 32 + lane];
        float4 w3 = W4[(k + 3) * 32 + lane];
#pragma unroll
        for (int e = 0; e < 4; e++) {
            float4 fv = *(const float4*)(fb + e * E_FEAT + k);
            acc[e][0] = fmaf(fv.w, w3.x, fmaf(fv.z, w2.x, fmaf(fv.y, w1.x, fmaf(fv.x, w0.x, acc[e][0]))));
            acc[e][1] = fmaf(fv.w, w3.y, fmaf(fv.z, w2.y, fmaf(fv.y, w1.y, fmaf(fv.x, w0.y, acc[e][1]))));
            acc[e][2] = fmaf(fv.w, w3.z, fmaf(fv.z, w2.z, fmaf(fv.y, w1.z, fmaf(fv.x, w0.z, acc[e][2]))));
            acc[e][3] = fmaf(fv.w, w3.w, fmaf(fv.z, w2.w, fmaf(fv.y, w1.w, fmaf(fv.x, w0.w, acc[e][3]))));
        }
    }

    // bias
    float4 bv = ((const float4*)eb)[lane];
#pragma unroll
    for (int e = 0; e < 4; e++) {
        acc[e][0] += bv.x; acc[e][1] += bv.y; acc[e][2] += bv.z; acc[e][3] += bv.w;
    }

    // layernorm per edge (warp holds all 128 channels of its 4 edges)
    float red[4];
#pragma unroll
    for (int e = 0; e < 4; e++) red[e] = acc[e][0] + acc[e][1] + acc[e][2] + acc[e][3];
#pragma unroll
    for (int o = 16; o > 0; o >>= 1)
#pragma unroll
        for (int e = 0; e < 4; e++) red[e] += __shfl_xor_sync(0xffffffffu, red[e], o);
    float mean[4];
#pragma unroll
    for (int e = 0; e < 4; e++) mean[e] = red[e] * (1.0f / HIDDEN);
    float vr[4];
#pragma unroll
    for (int e = 0; e < 4; e++) {
        float v = 0.f;
#pragma unroll
        for (int j = 0; j < 4; j++) { float d = acc[e][j] - mean[e]; v += d * d; }
        vr[e] = v;
    }
#pragma unroll
    for (int o = 16; o > 0; o >>= 1)
#pragma unroll
        for (int e = 0; e < 4; e++) vr[e] += __shfl_xor_sync(0xffffffffu, vr[e], o);

    float4 lw = ((const float4*)lnw)[lane];
    float4 lb = ((const float4*)lnb)[lane];
#pragma unroll
    for (int e = 0; e < 4; e++) {
        float inv = 1.0f / sqrtf(vr[e] * (1.0f / HIDDEN) + 1e-5f);
        int eg = tile + ty * 4 + e;
        float4 o4;
        o4.x = (acc[e][0] - mean[e]) * inv * lw.x + lb.x;
        o4.y = (acc[e][1] - mean[e]) * inv * lw.y + lb.y;
        o4.z = (acc[e][2] - mean[e]) * inv * lw.z + lb.z;
        o4.w = (acc[e][3] - mean[e]) * inv * lw.w + lb.w;
        ((float4*)(out + (size_t)eg * HIDDEN))[lane] = o4;
    }
}

// ---------------------------------------------------------------------------
extern "C" void kernel_launch(void* const* d_in, const int* in_sizes, int n_in,
                              void* d_out, int out_size) {
    const float* coords     = (const float*)d_in[0];
    const float* cX         = (const float*)d_in[1];
    const float* node_W     = (const float*)d_in[2];
    const float* node_b     = (const float*)d_in[3];
    const float* node_ln_w  = (const float*)d_in[4];
    const float* node_ln_b  = (const float*)d_in[5];
    const float* edge_W     = (const float*)d_in[6];
    const float* edge_b     = (const float*)d_in[7];
    const float* edge_ln_w  = (const float*)d_in[8];
    const float* edge_ln_b  = (const float*)d_in[9];
    const int*   batch      = (const int*)d_in[10];
    const int*   edge_index = (const int*)d_in[11];
    float* out = (float*)d_out;

    frames_kernel<<<(N_RES + 255) / 256, 256>>>(cX, batch);
    node_kernel<<<N_RES / 8, 256>>>(coords, cX, node_W, node_b, node_ln_w, node_ln_b,
                                    batch, out);
    edge_kernel<<<N_EDGES / 16, 128>>>(coords, edge_W, edge_b, edge_ln_w, edge_ln_b,
                                       edge_index, out + (size_t)N_RES * HIDDEN);
}